// round 1
// baseline (speedup 1.0000x reference)
#include <cuda_runtime.h>
#include <math_constants.h>

#define EMB 128
#define MAXB 1024
#define NW 8          // warps per block in pooling kernel
#define GPB 8         // graphs per block in MLP kernel

// Scratch (device globals; no allocation allowed)
__device__ float g_s[MAXB * EMB];
__device__ float g_flag[MAXB];

__device__ __forceinline__ int lower_bound_i(const int* __restrict__ a, int n, int v) {
    int lo = 0, hi = n;
    while (lo < hi) {
        int mid = (lo + hi) >> 1;
        if (a[mid] < v) lo = mid + 1; else hi = mid;
    }
    return lo;
}

// ---------------------------------------------------------------------------
// Kernel 1: per-graph softmax-weighted pooling of x rows.
//   s_b = sum_i exp(gate_i - m) * x_i / sum_i exp(gate_i - m)   (online softmax)
// grid = B blocks, 256 threads (8 warps). Each warp processes whole rows.
// ---------------------------------------------------------------------------
__global__ __launch_bounds__(256) void k_pool(
    const float* __restrict__ x, const int* __restrict__ bidx,
    const float* __restrict__ Wg, const float* __restrict__ bg, int N)
{
    int b = blockIdx.x;
    int start = lower_bound_i(bidx, N, b);
    int end   = lower_bound_i(bidx, N, b + 1);

    int lane = threadIdx.x & 31;
    int w    = threadIdx.x >> 5;

    float4 wg  = ((const float4*)Wg)[lane];
    float  bg0 = bg[0];

    float4 acc = make_float4(0.f, 0.f, 0.f, 0.f);
    float denom = 0.f;
    float m = -CUDART_INF_F;

    for (int i = start + w; i < end; i += NW) {
        float4 v = __ldg(((const float4*)(x + (size_t)i * EMB)) + lane);
        float p = v.x * wg.x + v.y * wg.y + v.z * wg.z + v.w * wg.w;
        #pragma unroll
        for (int off = 16; off; off >>= 1)
            p += __shfl_xor_sync(0xffffffffu, p, off);
        float gate = p + bg0;
        if (gate > m) {                       // warp-uniform branch
            float r = __expf(m - gate);       // first iter: exp(-inf)=0
            acc.x *= r; acc.y *= r; acc.z *= r; acc.w *= r;
            denom *= r;
            m = gate;
        }
        float e = __expf(gate - m);
        acc.x += e * v.x; acc.y += e * v.y; acc.z += e * v.z; acc.w += e * v.w;
        denom += e;
    }

    __shared__ float sm_acc[NW][EMB];
    __shared__ float sm_m[NW], sm_d[NW];
    ((float4*)sm_acc[w])[lane] = acc;
    if (lane == 0) { sm_m[w] = m; sm_d[w] = denom; }
    __syncthreads();

    if (threadIdx.x < EMB) {
        float M = -CUDART_INF_F;
        #pragma unroll
        for (int j = 0; j < NW; j++) M = fmaxf(M, sm_m[j]);
        float s = 0.f, d = 0.f;
        if (M > -CUDART_INF_F) {
            #pragma unroll
            for (int j = 0; j < NW; j++) {
                float r = __expf(sm_m[j] - M);   // empty warp: exp(-inf)=0
                s += sm_acc[j][threadIdx.x] * r;
                d += sm_d[j] * r;
            }
        }
        float outv = (d > 0.f) ? (s / d) : 0.f;
        g_s[b * EMB + threadIdx.x] = outv;
        if (threadIdx.x == 0) g_flag[b] = (d > 0.f) ? 1.f : 0.f;
    }
}

// ---------------------------------------------------------------------------
// Kernel 2:
//   g   = s @ Wv + bv          (zeroed for empty segments, matching reference)
//   h   = g @ Wm[0:128] + g_prev @ Wm[128:256] + bm
//   out = g_prev + leaky_relu(h, 0.01)
// grid = B/GPB blocks, 256 threads. Weights staged in dynamic smem (72 KB).
// Thread (gh, j): j = col 0..127, gh selects 4 of the 8 graphs.
// ---------------------------------------------------------------------------
extern __shared__ float smem2[];

__global__ __launch_bounds__(256) void k_mlp(
    const float* __restrict__ gp, const float* __restrict__ Wv,
    const float* __restrict__ bv, const float* __restrict__ Wm,
    const float* __restrict__ bm, float* __restrict__ out)
{
    float* Wsh = smem2;                 // 128*128 floats
    float* ssh = Wsh + EMB * EMB;       // GPB*128 floats (s rows, then g_prev rows)
    float* gsh = ssh + GPB * EMB;       // GPB*128 floats (pooled g)

    int gbase = blockIdx.x * GPB;
    int j  = threadIdx.x & 127;
    int gh = threadIdx.x >> 7;          // 0 or 1

    const float4* Wv4 = (const float4*)Wv;
    const float4* Wm4 = (const float4*)Wm;
    float4* Wsh4 = (float4*)Wsh;
    float4* ssh4 = (float4*)ssh;

    // stage Wv + s rows
    for (int i = threadIdx.x; i < EMB * EMB / 4; i += 256) Wsh4[i] = Wv4[i];
    {
        const float4* s4 = (const float4*)(g_s + (size_t)gbase * EMB);
        for (int i = threadIdx.x; i < GPB * EMB / 4; i += 256) ssh4[i] = s4[i];
    }
    __syncthreads();

    float bvj = bv[j];
    float gacc[4] = {0.f, 0.f, 0.f, 0.f};
    #pragma unroll 4
    for (int k = 0; k < EMB; k++) {
        float wkj = Wsh[k * EMB + j];
        #pragma unroll
        for (int t = 0; t < 4; t++)
            gacc[t] += ssh[(gh * 4 + t) * EMB + k] * wkj;
    }
    #pragma unroll
    for (int t = 0; t < 4; t++) {
        int gl = gh * 4 + t;
        float fl = g_flag[gbase + gl];
        gsh[gl * EMB + j] = (fl != 0.f) ? (gacc[t] + bvj) : 0.f;
    }
    __syncthreads();

    // stage Wm_top + g_prev rows (ssh reused)
    for (int i = threadIdx.x; i < EMB * EMB / 4; i += 256) Wsh4[i] = Wm4[i];
    {
        const float4* gp4 = (const float4*)(gp + (size_t)gbase * EMB);
        for (int i = threadIdx.x; i < GPB * EMB / 4; i += 256) ssh4[i] = gp4[i];
    }
    __syncthreads();

    float hacc[4] = {0.f, 0.f, 0.f, 0.f};
    #pragma unroll 4
    for (int k = 0; k < EMB; k++) {
        float wkj = Wsh[k * EMB + j];
        #pragma unroll
        for (int t = 0; t < 4; t++)
            hacc[t] += gsh[(gh * 4 + t) * EMB + k] * wkj;
    }
    __syncthreads();

    // stage Wm_bot
    for (int i = threadIdx.x; i < EMB * EMB / 4; i += 256) Wsh4[i] = Wm4[EMB * EMB / 4 + i];
    __syncthreads();

    #pragma unroll 4
    for (int k = 0; k < EMB; k++) {
        float wkj = Wsh[k * EMB + j];
        #pragma unroll
        for (int t = 0; t < 4; t++)
            hacc[t] += ssh[(gh * 4 + t) * EMB + k] * wkj;
    }

    float bmj = bm[j];
    #pragma unroll
    for (int t = 0; t < 4; t++) {
        int gl = gh * 4 + t;
        float h = hacc[t] + bmj;
        float lr = (h > 0.f) ? h : 0.01f * h;
        out[(size_t)(gbase + gl) * EMB + j] = ssh[gl * EMB + j] + lr;
    }
}

extern "C" void kernel_launch(void* const* d_in, const int* in_sizes, int n_in,
                              void* d_out, int out_size)
{
    const float* x    = (const float*)d_in[0];
    const float* gp   = (const float*)d_in[1];
    const int*   bidx = (const int*)  d_in[2];
    const float* Wg   = (const float*)d_in[3];
    const float* bg   = (const float*)d_in[4];
    const float* Wv   = (const float*)d_in[5];
    const float* bv   = (const float*)d_in[6];
    const float* Wm   = (const float*)d_in[7];
    const float* bm   = (const float*)d_in[8];
    float* out = (float*)d_out;

    int N = in_sizes[0] / EMB;
    int B = in_sizes[1] / EMB;

    const int smem_bytes = (EMB * EMB + 2 * GPB * EMB) * (int)sizeof(float); // 73728
    cudaFuncSetAttribute(k_mlp, cudaFuncAttributeMaxDynamicSharedMemorySize, smem_bytes);

    k_pool<<<B, 256>>>(x, bidx, Wg, bg, N);
    k_mlp<<<B / GPB, 256, smem_bytes>>>(gp, Wv, bv, Wm, bm, out);
}